// round 2
// baseline (speedup 1.0000x reference)
#include <cuda_runtime.h>
#include <math.h>
#include <stdint.h>

#define Nn 51200
#define Ee 819200
#define Bb 64

// ---------------- scratch (__device__ globals; allocation-free) ----------------
struct __align__(32) EdgeRec { float4 basis; int src; int widx; int p0; int p1; };

__device__ int     d_cnt[Nn];
__device__ int     d_cur[Nn];
__device__ int     d_off[Nn + 1];
__device__ EdgeRec d_edge[Ee];
__device__ float   d_W1p[192 * 32];          // rows 0..174 = W1 flat, 175..181 = root1, rest 0
__device__ float   d_W2p[832 * 64];          // rows 0..799 = W2 flat, 800..831 = root2
__device__ float   d_U1[(size_t)Nn * 192];
__device__ float   d_h1[(size_t)Nn * 32];
__device__ float   d_U2[(size_t)Nn * 832];
__device__ float   d_h2[(size_t)Nn * 64];

__device__ __forceinline__ float eluf(float v) { return v > 0.f ? v : (expf(v) - 1.f); }

// packed fp32x2 FMA (Blackwell): d = a*b + d, two fp32 lanes per instruction
__device__ __forceinline__ void ffma2(unsigned long long& d, unsigned long long a,
                                      unsigned long long b) {
    asm("fma.rn.f32x2 %0, %1, %2, %0;" : "+l"(d) : "l"(a), "l"(b));
}
__device__ __forceinline__ unsigned long long pack2(float x, float y) {
    unsigned long long r;
    asm("mov.b64 %0, {%1, %2};" : "=l"(r) : "f"(x), "f"(y));
    return r;
}

// ---------------- CSR build ----------------
__global__ void k_zero() {
    int i = blockIdx.x * blockDim.x + threadIdx.x;
    if (i < Nn) { d_cnt[i] = 0; d_cur[i] = 0; }
}

__global__ void k_hist(const int* __restrict__ dst) {
    int e = blockIdx.x * blockDim.x + threadIdx.x;
    if (e < Ee) atomicAdd(&d_cnt[dst[e]], 1);
}

__global__ void k_scan() {
    __shared__ int s[1024];
    int t = threadIdx.x;
    const int CH = (Nn + 1023) / 1024;  // 50
    int base = t * CH;
    int sum = 0;
    for (int j = 0; j < CH; j++) {
        int idx = base + j;
        if (idx < Nn) sum += d_cnt[idx];
    }
    s[t] = sum;
    __syncthreads();
    for (int ofs = 1; ofs < 1024; ofs <<= 1) {
        int v = (t >= ofs) ? s[t - ofs] : 0;
        __syncthreads();
        if (t >= ofs) s[t] += v;
        __syncthreads();
    }
    int run = (t == 0) ? 0 : s[t - 1];
    for (int j = 0; j < CH; j++) {
        int idx = base + j;
        if (idx < Nn) { d_off[idx] = run; run += d_cnt[idx]; }
    }
    if (t == 1023) d_off[Nn] = run;
}

__global__ void k_scatter(const int* __restrict__ src, const int* __restrict__ dst,
                          const float* __restrict__ pseudo) {
    int e = blockIdx.x * blockDim.x + threadIdx.x;
    if (e >= Ee) return;
    int d = dst[e];
    int pos = d_off[d] + atomicAdd(&d_cur[d], 1);
    float v0 = pseudo[2 * e] * 4.f;
    float v1 = pseudo[2 * e + 1] * 4.f;
    int lo0 = __float2int_rd(v0); lo0 = lo0 < 0 ? 0 : (lo0 > 3 ? 3 : lo0);
    int lo1 = __float2int_rd(v1); lo1 = lo1 < 0 ? 0 : (lo1 > 3 ? 3 : lo1);
    float f0 = v0 - (float)lo0, f1 = v1 - (float)lo1;
    float g0 = 1.f - f0, g1 = 1.f - f1;
    int k0 = lo0 * 5 + lo1;
    int wx = k0 | ((k0 + 1) << 8) | ((k0 + 5) << 16) | ((k0 + 6) << 24);
    *(float4*)&d_edge[pos].basis = make_float4(g0 * g1, g0 * f1, f0 * g1, f0 * f1);
    *(int4*)&d_edge[pos].src = make_int4(src[e], wx, 0, 0);
}

// ---------------- weight prep (fold root into GEMM weights) ----------------
__global__ void k_wprep(const float* __restrict__ W1, const float* __restrict__ root1,
                        const float* __restrict__ W2, const float* __restrict__ root2) {
    int j = blockIdx.x * blockDim.x + threadIdx.x;
    if (j < 192 * 32) {
        float v = 0.f;
        if (j < 5600) v = W1[j];
        else if (j < 5824) v = root1[j - 5600];
        d_W1p[j] = v;
    }
    if (j < 832 * 64) {
        float v;
        if (j < 51200) v = W2[j];
        else v = root2[j - 51200];
        d_W2p[j] = v;
    }
}

// ---------------- U1 build: per node accumulate u[k*7+i], 4 edges in flight ----------------
__global__ void k_u1(const float* __restrict__ x) {
    __shared__ float su[8][4][176];
    int tid = threadIdx.x;
    int warp = tid >> 5, lane = tid & 31;
    int n = blockIdx.x * 8 + warp;
    if (n >= Nn) return;
    float(*u)[176] = su[warp];
    for (int j = lane; j < 4 * 176; j += 32) ((float*)u)[j] = 0.f;
    __syncwarp();
    int beg = d_off[n], end = d_off[n + 1];
    int eb = lane / 7, i = lane - eb * 7;
    if (lane < 28) {
        for (int p0 = beg; p0 < end; p0 += 4) {
            int p = p0 + eb;
            if (p < end) {
                float4 bs = *(const float4*)&d_edge[p].basis;
                int2 sw = *(const int2*)&d_edge[p].src;
                int sv = sw.x, wx = sw.y;
                float xv = x[sv * 7 + i];
                u[eb][(wx & 255) * 7 + i]         += bs.x * xv;
                u[eb][((wx >> 8) & 255) * 7 + i]  += bs.y * xv;
                u[eb][((wx >> 16) & 255) * 7 + i] += bs.z * xv;
                u[eb][((wx >> 24) & 255) * 7 + i] += bs.w * xv;
            }
        }
    }
    __syncwarp();
    float inv = 1.f / fmaxf((float)(end - beg), 1.f);
    for (int j = lane; j < 192; j += 32) {
        float v;
        if (j < 175)      v = (u[0][j] + u[1][j] + u[2][j] + u[3][j]) * inv;
        else if (j < 182) v = x[n * 7 + (j - 175)];
        else              v = 0.f;
        d_U1[(size_t)n * 192 + j] = v;
    }
}

// ---------------- U2 build: lane = channel, lane-exclusive smem slots ----------------
__global__ void k_u2() {
    __shared__ float su[8][800];
    int tid = threadIdx.x;
    int warp = tid >> 5, lane = tid & 31;
    int n = blockIdx.x * 8 + warp;
    if (n >= Nn) return;
    float* u = su[warp];
    for (int j = lane; j < 800; j += 32) u[j] = 0.f;
    __syncwarp();
    int beg = d_off[n], end = d_off[n + 1];
    for (int p = beg; p < end; p++) {
        float4 bs = *(const float4*)&d_edge[p].basis;
        int2 sw = *(const int2*)&d_edge[p].src;
        int sv = sw.x, wx = sw.y;
        float hv = d_h1[(size_t)sv * 32 + lane];
        u[(wx & 255) * 32 + lane]         += bs.x * hv;
        u[((wx >> 8) & 255) * 32 + lane]  += bs.y * hv;
        u[((wx >> 16) & 255) * 32 + lane] += bs.z * hv;
        u[((wx >> 24) & 255) * 32 + lane] += bs.w * hv;
    }
    __syncwarp();
    float inv = 1.f / fmaxf((float)(end - beg), 1.f);
    for (int j = lane; j < 832; j += 32) {
        float v = (j < 800) ? u[j] * inv : d_h1[(size_t)n * 32 + (j - 800)];
        d_U2[(size_t)n * 832 + j] = v;
    }
}

// ---------------- GEMM1: h1 = elu(U1(N,192) @ W1p(192,32) + b1) ----------------
// block 256 thr (8 warps), tile M=128. warp: 16 rows x 32 cols. f32x2 FMA.
__global__ void __launch_bounds__(256) k_gemm1(const float* __restrict__ b1) {
    __shared__ float As[2][32][128];
    __shared__ float Wt[2][32][32];
    const int tid = threadIdx.x, lane = tid & 31, warp = tid >> 5;
    const int m0 = blockIdx.x * 128;
    const int r = tid & 127, g = tid >> 7;          // A staging: g in {0,1}, 16 k each
    const int wr = tid >> 3, wc = (tid & 7) * 4;    // W staging
    const int r0 = warp * 16;
    const int c  = lane;
    unsigned long long acc[8];
#pragma unroll
    for (int i = 0; i < 8; i++) acc[i] = 0ULL;

    const float* aRow = &d_U1[(size_t)(m0 + r) * 192 + g * 16];

#define STAGE1(BUF, KB)                                                            \
    {                                                                              \
        float4 v0 = *(const float4*)(aRow + (KB));                                 \
        float4 v1 = *(const float4*)(aRow + (KB) + 4);                             \
        float4 v2 = *(const float4*)(aRow + (KB) + 8);                             \
        float4 v3 = *(const float4*)(aRow + (KB) + 12);                            \
        As[BUF][g * 16 + 0][r] = v0.x;  As[BUF][g * 16 + 1][r] = v0.y;             \
        As[BUF][g * 16 + 2][r] = v0.z;  As[BUF][g * 16 + 3][r] = v0.w;             \
        As[BUF][g * 16 + 4][r] = v1.x;  As[BUF][g * 16 + 5][r] = v1.y;             \
        As[BUF][g * 16 + 6][r] = v1.z;  As[BUF][g * 16 + 7][r] = v1.w;             \
        As[BUF][g * 16 + 8][r] = v2.x;  As[BUF][g * 16 + 9][r] = v2.y;             \
        As[BUF][g * 16 + 10][r] = v2.z; As[BUF][g * 16 + 11][r] = v2.w;            \
        As[BUF][g * 16 + 12][r] = v3.x; As[BUF][g * 16 + 13][r] = v3.y;            \
        As[BUF][g * 16 + 14][r] = v3.z; As[BUF][g * 16 + 15][r] = v3.w;            \
        *(float4*)&Wt[BUF][wr][wc] = *(const float4*)&d_W1p[((KB) + wr) * 32 + wc];\
    }

    STAGE1(0, 0)
    __syncthreads();
    int buf = 0;
    for (int kb = 0; kb < 192; kb += 32) {
        if (kb + 32 < 192) { int nb = buf ^ 1; STAGE1(nb, kb + 32) }
#pragma unroll
        for (int kk = 0; kk < 32; kk++) {
            const ulonglong2* ap = (const ulonglong2*)&As[buf][kk][r0];
            ulonglong2 q0 = ap[0], q1 = ap[1], q2 = ap[2], q3 = ap[3];
            float w = Wt[buf][kk][c];
            unsigned long long w2 = pack2(w, w);
            ffma2(acc[0], q0.x, w2); ffma2(acc[1], q0.y, w2);
            ffma2(acc[2], q1.x, w2); ffma2(acc[3], q1.y, w2);
            ffma2(acc[4], q2.x, w2); ffma2(acc[5], q2.y, w2);
            ffma2(acc[6], q3.x, w2); ffma2(acc[7], q3.y, w2);
        }
        __syncthreads();
        buf ^= 1;
    }
    float bv = b1[c];
#pragma unroll
    for (int rr = 0; rr < 8; rr++) {
        float lo, hi;
        asm("mov.b64 {%0,%1}, %2;" : "=f"(lo), "=f"(hi) : "l"(acc[rr]));
        d_h1[(size_t)(m0 + r0 + 2 * rr) * 32 + c]     = eluf(lo + bv);
        d_h1[(size_t)(m0 + r0 + 2 * rr + 1) * 32 + c] = eluf(hi + bv);
    }
#undef STAGE1
}

// ---------------- GEMM2: h2 = elu(U2(N,832) @ W2p(832,64) + b2) ----------------
// block 512 thr (16 warps), tile M=128 x 64. warp: 16 rows x 32 cols. f32x2 FMA.
__global__ void __launch_bounds__(512) k_gemm2(const float* __restrict__ b2) {
    __shared__ float As[2][32][128];
    __shared__ float Wt[2][32][64];
    const int tid = threadIdx.x, lane = tid & 31, warp = tid >> 5;
    const int m0 = blockIdx.x * 128;
    const int r = tid & 127, g = tid >> 7;          // A staging: g in 0..3, 8 k each
    const int wr = tid >> 4, wc = (tid & 15) * 4;   // W staging
    const int r0 = (warp >> 1) * 16;
    const int c  = (warp & 1) * 32 + lane;
    unsigned long long acc[8];
#pragma unroll
    for (int i = 0; i < 8; i++) acc[i] = 0ULL;

    const float* aRow = &d_U2[(size_t)(m0 + r) * 832 + g * 8];

#define STAGE2(BUF, KB)                                                            \
    {                                                                              \
        float4 v0 = *(const float4*)(aRow + (KB));                                 \
        float4 v1 = *(const float4*)(aRow + (KB) + 4);                             \
        As[BUF][g * 8 + 0][r] = v0.x; As[BUF][g * 8 + 1][r] = v0.y;                \
        As[BUF][g * 8 + 2][r] = v0.z; As[BUF][g * 8 + 3][r] = v0.w;                \
        As[BUF][g * 8 + 4][r] = v1.x; As[BUF][g * 8 + 5][r] = v1.y;                \
        As[BUF][g * 8 + 6][r] = v1.z; As[BUF][g * 8 + 7][r] = v1.w;                \
        *(float4*)&Wt[BUF][wr][wc] = *(const float4*)&d_W2p[((KB) + wr) * 64 + wc];\
    }

    STAGE2(0, 0)
    __syncthreads();
    int buf = 0;
    for (int kb = 0; kb < 832; kb += 32) {
        if (kb + 32 < 832) { int nb = buf ^ 1; STAGE2(nb, kb + 32) }
#pragma unroll
        for (int kk = 0; kk < 32; kk++) {
            const ulonglong2* ap = (const ulonglong2*)&As[buf][kk][r0];
            ulonglong2 q0 = ap[0], q1 = ap[1], q2 = ap[2], q3 = ap[3];
            float w = Wt[buf][kk][c];
            unsigned long long w2 = pack2(w, w);
            ffma2(acc[0], q0.x, w2); ffma2(acc[1], q0.y, w2);
            ffma2(acc[2], q1.x, w2); ffma2(acc[3], q1.y, w2);
            ffma2(acc[4], q2.x, w2); ffma2(acc[5], q2.y, w2);
            ffma2(acc[6], q3.x, w2); ffma2(acc[7], q3.y, w2);
        }
        __syncthreads();
        buf ^= 1;
    }
    float bv = b2[c];
#pragma unroll
    for (int rr = 0; rr < 8; rr++) {
        float lo, hi;
        asm("mov.b64 {%0,%1}, %2;" : "=f"(lo), "=f"(hi) : "l"(acc[rr]));
        d_h2[(size_t)(m0 + r0 + 2 * rr) * 64 + c]     = eluf(lo + bv);
        d_h2[(size_t)(m0 + r0 + 2 * rr + 1) * 64 + c] = eluf(hi + bv);
    }
#undef STAGE2
}

// ---------------- pooling + FC + log_softmax ----------------
__global__ void k_head(const int* __restrict__ slices, const float* __restrict__ fcw,
                       const float* __restrict__ fcb, float* __restrict__ out) {
    int b = blockIdx.x;
    int s0 = slices[b], s1 = slices[b + 1];
    __shared__ float red[4][64];
    __shared__ float g[64];
    __shared__ float lg[30];
    int tid = threadIdx.x;  // 256
    int o = tid & 63, part = tid >> 6;
    float acc = 0.f;
    for (int n = s0 + part; n < s1; n += 4) acc += d_h2[(size_t)n * 64 + o];
    red[part][o] = acc;
    __syncthreads();
    if (part == 0) {
        float s = red[0][o] + red[1][o] + red[2][o] + red[3][o];
        g[o] = s / fmaxf((float)(s1 - s0), 1.f);
    }
    __syncthreads();
    if (tid < 30) {
        float l = fcb[tid];
        for (int i = 0; i < 64; i++) l += g[i] * fcw[i * 30 + tid];
        lg[tid] = l;
    }
    __syncthreads();
    if (tid < 30) {
        float m = -1e30f;
        for (int j = 0; j < 30; j++) m = fmaxf(m, lg[j]);
        float se = 0.f;
        for (int j = 0; j < 30; j++) se += expf(lg[j] - m);
        out[b * 30 + tid] = lg[tid] - m - logf(se);
    }
}

// ---------------- launch ----------------
extern "C" void kernel_launch(void* const* d_in, const int* in_sizes, int n_in,
                              void* d_out, int out_size) {
    const float* x      = (const float*)d_in[0];
    const int*   eidx   = (const int*)d_in[1];
    const float* pseudo = (const float*)d_in[2];
    const int*   slices = (const int*)d_in[3];
    const float* W1     = (const float*)d_in[4];
    const float* root1  = (const float*)d_in[5];
    const float* b1     = (const float*)d_in[6];
    const float* W2     = (const float*)d_in[7];
    const float* root2  = (const float*)d_in[8];
    const float* b2     = (const float*)d_in[9];
    const float* fcw    = (const float*)d_in[10];
    const float* fcb    = (const float*)d_in[11];
    float* out = (float*)d_out;

    const int* src = eidx;
    const int* dst = eidx + Ee;

    k_zero<<<(Nn + 255) / 256, 256>>>();
    k_hist<<<(Ee + 1023) / 1024, 1024>>>(dst);
    k_scan<<<1, 1024>>>();
    k_scatter<<<(Ee + 1023) / 1024, 1024>>>(src, dst, pseudo);
    k_wprep<<<(832 * 64 + 255) / 256, 256>>>(W1, root1, W2, root2);
    k_u1<<<Nn / 8, 256>>>(x);
    k_gemm1<<<Nn / 128, 256>>>(b1);
    k_u2<<<Nn / 8, 256>>>();
    k_gemm2<<<Nn / 128, 512>>>(b2);
    k_head<<<Bb, 256>>>(slices, fcw, fcb, out);
}